// round 1
// baseline (speedup 1.0000x reference)
#include <cuda_runtime.h>
#include <math.h>
#include <math_constants.h>

#define IMG   512
#define NB    16
#define OT    74          // owned (output) tile
#define RG    96          // region = OT + 2*HALO
#define HALO  11          // 1 (boundary) + 10 (dilation cascade)
#define TPD   7           // ceil(512/74)
#define NTILES (NB*TPD*TPD)
#define RSTR  97          // smem row stride (conflict-free for column walks)
#define CSTR  75          // center buffer stride (odd -> conflict-free)
#define NTHR  288         // 9 warps; 96*96/288 = 32 px/thread exactly

#define AIDX(r,c) ((r)*RSTR+(c))

#define OFF_AG  (RG*RSTR)            // 9312
#define OFF_BP  (2*RG*RSTR)
#define OFF_BG  (3*RG*RSTR)
#define OFF_CP  (4*RG*RSTR)          // 37248
#define OFF_CG  (OFF_CP + OT*CSTR)   // +5550
#define OFF_RED (OFF_CG + OT*CSTR)
#define SMEM_FLOATS (OFF_RED + 48)
#define SMEM_BYTES  (SMEM_FLOATS*4)  // ~193.7 KB -> 1 CTA/SM

// accumulators: [0]=bce_sum, [1]=hd_sum, [2..17]=sum_p, [18..33]=sum_t, [34..49]=sum_pt
__device__ double g_acc[50];

__global__ void k_zero() {
    if (threadIdx.x < 50) g_acc[threadIdx.x] = 0.0;
}

// vertical max3 sliding pass: dst = vmax3(src) along one column, 32 rows
__device__ __forceinline__ void vpass3(const float* __restrict__ src,
                                       float* __restrict__ dst,
                                       int c, int r0) {
    float prev = src[AIDX(r0 > 0 ? r0 - 1 : 0, c)];
    float cur  = src[AIDX(r0, c)];
#pragma unroll
    for (int i = 0; i < 32; i++) {
        int r = r0 + i;
        float nxt = src[AIDX(r < RG - 1 ? r + 1 : RG - 1, c)];
        dst[AIDX(r, c)] = fmaxf(prev, fmaxf(cur, nxt));
        prev = cur; cur = nxt;
    }
}

// horizontal max3 sliding pass + fused |cur - other_boundary| accumulation
__device__ __forceinline__ float hpass3(const float* __restrict__ src,
                                        float* __restrict__ dst,
                                        const float* __restrict__ oc,
                                        int row, int c0, bool rowown, int ox) {
    float prev = src[AIDX(row, c0 > 0 ? c0 - 1 : 0)];
    float cur  = src[AIDX(row, c0)];
    float s = 0.f;
#pragma unroll
    for (int i = 0; i < 32; i++) {
        int c = c0 + i;
        float nxt = src[AIDX(row, c < RG - 1 ? c + 1 : RG - 1)];
        float v = fmaxf(prev, fmaxf(cur, nxt));
        dst[AIDX(row, c)] = v;
        if (rowown && (c >= HALO) && (c < HALO + OT) && ((ox + c) < IMG))
            s += fabsf(v - oc[(row - HALO) * CSTR + (c - HALO)]);
        prev = cur; cur = nxt;
    }
    return s;
}

__global__ void __launch_bounds__(NTHR, 1)
k_main(const float* __restrict__ logits, const int* __restrict__ target) {
    extern __shared__ float sm[];
    float* Ap  = sm;             // temp / raw p
    float* Ag  = sm + OFF_AG;    // temp / raw t
    float* Bp  = sm + OFF_BP;    // cur pred map
    float* Bg  = sm + OFF_BG;    // cur gt map
    float* Cp  = sm + OFF_CP;    // pred_b center (74x74)
    float* Cg  = sm + OFF_CG;    // gt_b center
    float* red = sm + OFF_RED;

    const int tid  = threadIdx.x;
    const int tile = blockIdx.x;
    const int b    = tile / (TPD * TPD);
    const int tr   = tile % (TPD * TPD);
    const int tyi  = tr / TPD, txi = tr % TPD;
    const int oy   = tyi * OT - HALO, ox = txi * OT - HALO;
    const bool interior = (oy >= 0) & (ox >= 0) & (oy + RG <= IMG) & (ox + RG <= IMG);

    const float* lg = logits + (size_t)b * IMG * IMG;
    const int*   tg = target + (size_t)b * IMG * IMG;

    float a_bce = 0.f, a_p = 0.f, a_t = 0.f, a_pt = 0.f, a_hd = 0.f;
    const float FINF = CUDART_INF_F;

    // ---- load phase: Ap = sigmoid(logits), Ag = t; elementwise loss partials on owned px
    for (int idx = tid; idx < RG * RG; idx += NTHR) {
        int r = idx / RG, c = idx - r * RG;
        int iy = oy + r, ix = ox + c;
        bool in = interior || ((iy >= 0) & (iy < IMG) & (ix >= 0) & (ix < IMG));
        float p = 0.f, t = 0.f;
        if (in) {
            float x = lg[iy * IMG + ix];
            t = (float)tg[iy * IMG + ix];
            p = 1.f / (1.f + expf(-x));
            if ((r >= HALO) & (r < HALO + OT) & (c >= HALO) & (c < HALO + OT)) {
                a_bce += fmaxf(x, 0.f) - x * t + log1pf(expf(-fabsf(x)));
                a_p += p; a_t += t; a_pt += p * t;
            }
        }
        Ap[AIDX(r, c)] = p;
        Ag[AIDX(r, c)] = t;
    }
    __syncthreads();

    // ---- boundary pass: B = maxpool3 - minpool3 (direct 3x3), -inf outside image
    for (int idx = tid; idx < RG * RG; idx += NTHR) {
        int r = idx / RG, c = idx - r * RG;
        int iy = oy + r, ix = ox + c;
        bool cin = interior || ((iy >= 0) & (iy < IMG) & (ix >= 0) & (ix < IMG));
        float bp = -FINF, bg = -FINF;
        if (cin) {
            float mxp = -FINF, mnp = FINF, mxg = -FINF, mng = FINF;
#pragma unroll
            for (int dr = -1; dr <= 1; dr++) {
                int rr = r + dr; rr = rr < 0 ? 0 : (rr > RG - 1 ? RG - 1 : rr);
                bool rin = interior || ((oy + rr >= 0) & (oy + rr < IMG));
#pragma unroll
                for (int dc = -1; dc <= 1; dc++) {
                    int cc = c + dc; cc = cc < 0 ? 0 : (cc > RG - 1 ? RG - 1 : cc);
                    bool nin = rin && (interior || ((ox + cc >= 0) & (ox + cc < IMG)));
                    float vp = Ap[AIDX(rr, cc)];
                    float vg = Ag[AIDX(rr, cc)];
                    mxp = fmaxf(mxp, nin ? vp : -FINF);
                    mnp = fminf(mnp, nin ? vp :  FINF);
                    mxg = fmaxf(mxg, nin ? vg : -FINF);
                    mng = fminf(mng, nin ? vg :  FINF);
                }
            }
            bp = mxp - mnp;   // >= 0 always (dil >= ero)
            bg = mxg - mng;
        }
        Bp[AIDX(r, c)] = bp;
        Bg[AIDX(r, c)] = bg;
        if ((r >= HALO) & (r < HALO + OT) & (c >= HALO) & (c < HALO + OT)) {
            Cp[(r - HALO) * CSTR + (c - HALO)] = bp;
            Cg[(r - HALO) * CSTR + (c - HALO)] = bg;
        }
    }
    __syncthreads();

    // ---- dilation cascade: maxpool_{2d+1}(b) via iterated separable 3x3, d = 1..10
    {
        const int cA   = tid % RG;  const int r0 = (tid / RG) * 32;
        const int rowB = tid % RG;  const int c0 = (tid / RG) * 32;
        const bool rowown = (rowB >= HALO) & (rowB < HALO + OT) & ((oy + rowB) < IMG);
        for (int d = 1; d <= 10; d++) {
            vpass3(Bp, Ap, cA, r0);
            vpass3(Bg, Ag, cA, r0);
            __syncthreads();
            float s = hpass3(Ap, Bp, Cg, rowB, c0, rowown, ox)   // |pred_d - gt_b|
                    + hpass3(Ag, Bg, Cp, rowB, c0, rowown, ox);  // |gt_d - pred_b|
            a_hd += (0.1f * (float)d) * s;
            __syncthreads();
        }
    }

    // ---- block reduction + global atomics
    const unsigned FULL = 0xffffffffu;
#pragma unroll
    for (int o = 16; o; o >>= 1) {
        a_bce += __shfl_down_sync(FULL, a_bce, o);
        a_p   += __shfl_down_sync(FULL, a_p,   o);
        a_t   += __shfl_down_sync(FULL, a_t,   o);
        a_pt  += __shfl_down_sync(FULL, a_pt,  o);
        a_hd  += __shfl_down_sync(FULL, a_hd,  o);
    }
    int lane = tid & 31, w = tid >> 5;
    if (lane == 0) {
        red[w] = a_bce; red[9 + w] = a_p; red[18 + w] = a_t;
        red[27 + w] = a_pt; red[36 + w] = a_hd;
    }
    __syncthreads();
    if (tid == 0) {
        float sb = 0, sp = 0, st = 0, spt = 0, sh = 0;
        for (int i = 0; i < 9; i++) {
            sb += red[i]; sp += red[9 + i]; st += red[18 + i];
            spt += red[27 + i]; sh += red[36 + i];
        }
        atomicAdd(&g_acc[0],      (double)sb);
        atomicAdd(&g_acc[1],      (double)sh);
        atomicAdd(&g_acc[2 + b],  (double)sp);
        atomicAdd(&g_acc[18 + b], (double)st);
        atomicAdd(&g_acc[34 + b], (double)spt);
    }
}

__global__ void k_final(float* out) {
    if (threadIdx.x == 0 && blockIdx.x == 0) {
        const double N = (double)NB * IMG * IMG;
        double bce = g_acc[0] / N;
        double hd  = (g_acc[1] / N) / (5.5 + 1e-8);   // weight_sum = sum d/10 = 5.5
        double ds = 0.0, fs = 0.0;
        for (int i = 0; i < 16; i++) {
            double p = g_acc[2 + i], t = g_acc[18 + i], pt = g_acc[34 + i];
            double dice = (2.0 * pt + 1e-6) / (p + t + 1e-6 + 1e-7);
            ds += 1.0 - dice;
            double FP = p - pt, FN = t - pt;
            double tv = (pt + 1e-6) / (pt + 0.7 * FP + 0.3 * FN + 1e-6 + 1e-7);
            fs += pow(1.0 - tv, 0.75);
        }
        out[0] = (float)(bce + ds / 16.0 + fs / 16.0 + 0.1 * hd);
    }
}

extern "C" void kernel_launch(void* const* d_in, const int* in_sizes, int n_in,
                              void* d_out, int out_size) {
    const float* logits = (const float*)d_in[0];
    const int*   target = (const int*)d_in[1];
    cudaFuncSetAttribute(k_main, cudaFuncAttributeMaxDynamicSharedMemorySize, SMEM_BYTES);
    k_zero<<<1, 64>>>();
    k_main<<<NTILES, NTHR, SMEM_BYTES>>>(logits, target);
    k_final<<<1, 32>>>((float*)d_out);
}

// round 2
// speedup vs baseline: 1.5604x; 1.5604x over previous
#include <cuda_runtime.h>
#include <math.h>
#include <math_constants.h>

#define IMG   512
#define NB    16
#define OT    74          // owned (output) tile
#define RG    96          // region = OT + 2*HALO
#define HALO  11          // 1 (boundary) + 10 (dilation cascade)
#define TPD   7
#define NTILES (NB*TPD*TPD)   // 784
#define RSTR2 97          // float2 row stride (odd -> conflict-free col walks)
#define CSTR2 75          // center buffer float2 stride (odd)
#define NTHR  576         // 18 warps; 96*96/576 = 16 px/thread
#define PXT   16

#define OFF_B2  (RG*RSTR2)            // 9312 (in float2)
#define OFF_C2  (2*RG*RSTR2)          // 18624
#define OFF_RED (OFF_C2 + OT*CSTR2)   // 24174
#define SMEM_F2 (OFF_RED + 48)
#define SMEM_BYTES (SMEM_F2*8)        // ~193.8 KB -> 1 CTA/SM

// per-tile partials: [tile][0]=bce [1]=hd [2]=p [3]=t [4]=pt  (fully rewritten every launch)
__device__ float g_part[NTILES*5];

__device__ __forceinline__ float2 fmax2(float2 a, float2 b) {
    return make_float2(fmaxf(a.x, b.x), fmaxf(a.y, b.y));
}

__global__ void __launch_bounds__(NTHR, 1)
k_main(const float* __restrict__ logits, const int* __restrict__ target) {
    extern __shared__ float2 sm[];
    float2* A2 = sm;             // temp (v-pass out) / raw (p,t)
    float2* B2 = sm + OFF_B2;    // current (pred,gt) maps
    float2* C2 = sm + OFF_C2;    // center boundaries (pred_b, gt_b), 74x74
    float*  red = (float*)(sm + OFF_RED);

    const int tid  = threadIdx.x;
    const int tile = blockIdx.x;
    const int b    = tile / (TPD * TPD);
    const int tr   = tile % (TPD * TPD);
    const int tyi  = tr / TPD, txi = tr % TPD;
    const int oy   = tyi * OT - HALO, ox = txi * OT - HALO;
    const bool interior = (oy >= 0) & (ox >= 0) & (oy + RG <= IMG) & (ox + RG <= IMG);

    const float* lg = logits + (size_t)b * IMG * IMG;
    const int*   tg = target + (size_t)b * IMG * IMG;

    float a_bce = 0.f, a_p = 0.f, a_t = 0.f, a_pt = 0.f, a_hd = 0.f;
    const float FINF = CUDART_INF_F;

    // ---- load: A2 = (sigmoid(x), t); elementwise loss partials on owned px
#pragma unroll
    for (int k = 0; k < PXT; k++) {
        int idx = tid + k * NTHR;
        int r = idx / RG, c = idx - r * RG;
        int iy = oy + r, ix = ox + c;
        bool in = interior || ((iy >= 0) & (iy < IMG) & (ix >= 0) & (ix < IMG));
        float p = 0.f, t = 0.f;
        if (in) {
            float x = lg[iy * IMG + ix];
            t = (float)tg[iy * IMG + ix];
            p = 1.f / (1.f + expf(-x));
            if ((r >= HALO) & (r < HALO + OT) & (c >= HALO) & (c < HALO + OT)) {
                a_bce += fmaxf(x, 0.f) - x * t + log1pf(expf(-fabsf(x)));
                a_p += p; a_t += t; a_pt += p * t;
            }
        }
        A2[r * RSTR2 + c] = make_float2(p, t);
    }
    __syncthreads();

    // ---- boundary: B = maxpool3 - minpool3 (-inf outside image)
#pragma unroll
    for (int k = 0; k < PXT; k++) {
        int idx = tid + k * NTHR;
        int r = idx / RG, c = idx - r * RG;
        int iy = oy + r, ix = ox + c;
        bool cin = interior || ((iy >= 0) & (iy < IMG) & (ix >= 0) & (ix < IMG));
        float2 bnd = make_float2(-FINF, -FINF);
        if (cin) {
            float mxp = -FINF, mnp = FINF, mxg = -FINF, mng = FINF;
#pragma unroll
            for (int dr = -1; dr <= 1; dr++) {
                int rr = r + dr; rr = rr < 0 ? 0 : (rr > RG - 1 ? RG - 1 : rr);
                bool rin = interior || ((oy + rr >= 0) & (oy + rr < IMG));
#pragma unroll
                for (int dc = -1; dc <= 1; dc++) {
                    int cc = c + dc; cc = cc < 0 ? 0 : (cc > RG - 1 ? RG - 1 : cc);
                    bool nin = rin && (interior || ((ox + cc >= 0) & (ox + cc < IMG)));
                    float2 v = A2[rr * RSTR2 + cc];
                    mxp = fmaxf(mxp, nin ? v.x : -FINF);
                    mnp = fminf(mnp, nin ? v.x :  FINF);
                    mxg = fmaxf(mxg, nin ? v.y : -FINF);
                    mng = fminf(mng, nin ? v.y :  FINF);
                }
            }
            bnd = make_float2(mxp - mnp, mxg - mng);
        }
        B2[r * RSTR2 + c] = bnd;
        if ((r >= HALO) & (r < HALO + OT) & (c >= HALO) & (c < HALO + OT))
            C2[(r - HALO) * CSTR2 + (c - HALO)] = bnd;
    }
    __syncthreads();

    // ---- dilation cascade: maxpool_{2d+1} via iterated separable 3x3, d = 1..10
    {
        const int cA  = tid % RG;  const int rA0 = (tid / RG) * PXT;
        const int rB  = tid % RG;  const int cB0 = (tid / RG) * PXT;
        const bool rowown = (rB >= HALO) & (rB < HALO + OT) & ((oy + rB) < IMG);
        const float2* crow = C2 + (rB - HALO) * CSTR2;

        for (int d = 1; d <= 10; d++) {
            // vertical max3: A2 = vmax3(B2), 16 rows of column cA
            {
                float2 prev = B2[(rA0 > 0 ? rA0 - 1 : 0) * RSTR2 + cA];
                float2 cur  = B2[rA0 * RSTR2 + cA];
#pragma unroll
                for (int i = 0; i < PXT; i++) {
                    int r = rA0 + i;
                    float2 nxt = B2[(r < RG - 1 ? r + 1 : RG - 1) * RSTR2 + cA];
                    A2[r * RSTR2 + cA] = fmax2(prev, fmax2(cur, nxt));
                    prev = cur; cur = nxt;
                }
            }
            __syncthreads();
            // horizontal max3: B2 = hmax3(A2), fused |.| accumulation on owned px
            {
                float2 prev = A2[rB * RSTR2 + (cB0 > 0 ? cB0 - 1 : 0)];
                float2 cur  = A2[rB * RSTR2 + cB0];
                float s = 0.f;
#pragma unroll
                for (int i = 0; i < PXT; i++) {
                    int c = cB0 + i;
                    float2 nxt = A2[rB * RSTR2 + (c < RG - 1 ? c + 1 : RG - 1)];
                    float2 v = fmax2(prev, fmax2(cur, nxt));
                    B2[rB * RSTR2 + c] = v;
                    if (rowown && (c >= HALO) && (c < HALO + OT) && ((ox + c) < IMG)) {
                        float2 cc = crow[c - HALO];  // (pred_b, gt_b)
                        s += fabsf(v.x - cc.y) + fabsf(v.y - cc.x);
                    }
                    prev = cur; cur = nxt;
                }
                a_hd += (0.1f * (float)d) * s;
            }
            __syncthreads();
        }
    }

    // ---- block reduction -> per-tile partials (no atomics)
    const unsigned FULL = 0xffffffffu;
#pragma unroll
    for (int o = 16; o; o >>= 1) {
        a_bce += __shfl_down_sync(FULL, a_bce, o);
        a_hd  += __shfl_down_sync(FULL, a_hd,  o);
        a_p   += __shfl_down_sync(FULL, a_p,   o);
        a_t   += __shfl_down_sync(FULL, a_t,   o);
        a_pt  += __shfl_down_sync(FULL, a_pt,  o);
    }
    int lane = tid & 31, w = tid >> 5;               // 18 warps
    if (lane == 0) {
        red[w] = a_bce; red[18 + w] = a_hd; red[36 + w] = a_p;
        red[54 + w] = a_t; red[72 + w] = a_pt;
    }
    __syncthreads();
    if (tid == 0) {
        float sb = 0, sh = 0, sp = 0, st = 0, spt = 0;
#pragma unroll
        for (int i = 0; i < 18; i++) {
            sb += red[i]; sh += red[18 + i]; sp += red[36 + i];
            st += red[54 + i]; spt += red[72 + i];
        }
        float* g = &g_part[tile * 5];
        g[0] = sb; g[1] = sh; g[2] = sp; g[3] = st; g[4] = spt;
    }
}

__global__ void k_final(float* __restrict__ out) {
    __shared__ double simg[16][2];   // (1-dice), ft per image
    __shared__ double sbh[16][2];    // bce, hd per image-group
    int w = threadIdx.x >> 5, lane = threadIdx.x & 31;
    if (w < 16) {
        double bce = 0, hd = 0, p = 0, t = 0, pt = 0;
        for (int i = lane; i < TPD * TPD; i += 32) {
            const float* g = &g_part[(w * TPD * TPD + i) * 5];
            bce += g[0]; hd += g[1]; p += g[2]; t += g[3]; pt += g[4];
        }
        const unsigned FULL = 0xffffffffu;
#pragma unroll
        for (int o = 16; o; o >>= 1) {
            bce += __shfl_down_sync(FULL, bce, o);
            hd  += __shfl_down_sync(FULL, hd,  o);
            p   += __shfl_down_sync(FULL, p,   o);
            t   += __shfl_down_sync(FULL, t,   o);
            pt  += __shfl_down_sync(FULL, pt,  o);
        }
        if (lane == 0) {
            double dice = (2.0 * pt + 1e-6) / (p + t + 1e-6 + 1e-7);
            double FP = p - pt, FN = t - pt;
            double tv = (pt + 1e-6) / (pt + 0.7 * FP + 0.3 * FN + 1e-6 + 1e-7);
            simg[w][0] = 1.0 - dice;
            simg[w][1] = pow(1.0 - tv, 0.75);
            sbh[w][0] = bce; sbh[w][1] = hd;
        }
    }
    __syncthreads();
    if (threadIdx.x == 0) {
        double ds = 0, fs = 0, sb = 0, sh = 0;
#pragma unroll
        for (int i = 0; i < 16; i++) {
            ds += simg[i][0]; fs += simg[i][1];
            sb += sbh[i][0];  sh += sbh[i][1];
        }
        const double N = (double)NB * IMG * IMG;
        out[0] = (float)(sb / N + ds / 16.0 + fs / 16.0 +
                         0.1 * ((sh / N) / (5.5 + 1e-8)));
    }
}

extern "C" void kernel_launch(void* const* d_in, const int* in_sizes, int n_in,
                              void* d_out, int out_size) {
    const float* logits = (const float*)d_in[0];
    const int*   target = (const int*)d_in[1];
    cudaFuncSetAttribute(k_main, cudaFuncAttributeMaxDynamicSharedMemorySize, SMEM_BYTES);
    k_main<<<NTILES, NTHR, SMEM_BYTES>>>(logits, target);
    k_final<<<1, 512>>>((float*)d_out);
}

// round 3
// speedup vs baseline: 1.7557x; 1.1251x over previous
#include <cuda_runtime.h>
#include <math.h>
#include <math_constants.h>

#define IMG   512
#define NB    16
#define OT    74          // owned (output) tile
#define RG    96          // region = OT + 2*HALO
#define HALO  11          // 1 (boundary) + 10 (dilation cascade)
#define TPD   7
#define NTILES (NB*TPD*TPD)   // 784
#define RSTR2 97          // float2 row stride (odd -> conflict-free col walks)
#define CSTR2 75          // center buffer float2 stride (odd)
#define NTHR  768         // 24 warps; 96*96/768 = 12 px/thread
#define PXT   12

#define OFF_B2  (RG*RSTR2)            // 9312 (in float2)
#define OFF_C2  (2*RG*RSTR2)          // 18624
#define OFF_RED (OFF_C2 + OT*CSTR2)   // 24174
#define SMEM_F2 (OFF_RED + 64)        // 120 floats for 24-warp reduction + flag
#define SMEM_BYTES (SMEM_F2*8)        // ~193.9 KB -> 1 CTA/SM

// per-tile partials: [tile][0]=bce [1]=hd [2]=p [3]=t [4]=pt (fully rewritten every launch)
__device__ float g_part[NTILES*5];
__device__ unsigned g_count;   // last-CTA counter; finisher resets to 0

__device__ __forceinline__ float2 fmax2(float2 a, float2 b) {
    return make_float2(fmaxf(a.x, b.x), fmaxf(a.y, b.y));
}

__global__ void __launch_bounds__(NTHR, 1)
k_main(const float* __restrict__ logits, const int* __restrict__ target,
       float* __restrict__ out) {
    extern __shared__ float2 sm[];
    float2* A2 = sm;             // temp (v-pass out) / raw (p,t)
    float2* B2 = sm + OFF_B2;    // current (pred,gt) maps
    float2* C2 = sm + OFF_C2;    // center boundaries (pred_b, gt_b), 74x74
    float*  red = (float*)(sm + OFF_RED);

    const int tid  = threadIdx.x;
    const int tile = blockIdx.x;
    const int b    = tile / (TPD * TPD);
    const int tr   = tile % (TPD * TPD);
    const int tyi  = tr / TPD, txi = tr % TPD;
    const int oy   = tyi * OT - HALO, ox = txi * OT - HALO;
    const bool interior = (oy >= 0) & (ox >= 0) & (oy + RG <= IMG) & (ox + RG <= IMG);

    const float* lg = logits + (size_t)b * IMG * IMG;
    const int*   tg = target + (size_t)b * IMG * IMG;

    float a_bce = 0.f, a_p = 0.f, a_t = 0.f, a_pt = 0.f, a_hd = 0.f;
    const float FINF = CUDART_INF_F;

    // ---- load: A2 = (sigmoid(x), t); elementwise loss partials on owned px
#pragma unroll
    for (int k = 0; k < PXT; k++) {
        int idx = tid + k * NTHR;
        int r = idx / RG, c = idx - r * RG;
        int iy = oy + r, ix = ox + c;
        bool in = interior || ((iy >= 0) & (iy < IMG) & (ix >= 0) & (ix < IMG));
        float p = 0.f, t = 0.f;
        if (in) {
            float x = lg[iy * IMG + ix];
            t = (float)tg[iy * IMG + ix];
            p = 1.f / (1.f + expf(-x));
            if ((r >= HALO) & (r < HALO + OT) & (c >= HALO) & (c < HALO + OT)) {
                a_bce += fmaxf(x, 0.f) - x * t + log1pf(expf(-fabsf(x)));
                a_p += p; a_t += t; a_pt += p * t;
            }
        }
        A2[r * RSTR2 + c] = make_float2(p, t);
    }
    __syncthreads();

    // ---- boundary: B = maxpool3 - minpool3 (-inf outside image)
#pragma unroll
    for (int k = 0; k < PXT; k++) {
        int idx = tid + k * NTHR;
        int r = idx / RG, c = idx - r * RG;
        int iy = oy + r, ix = ox + c;
        bool cin = interior || ((iy >= 0) & (iy < IMG) & (ix >= 0) & (ix < IMG));
        float2 bnd = make_float2(-FINF, -FINF);
        if (cin) {
            float mxp = -FINF, mnp = FINF, mxg = -FINF, mng = FINF;
#pragma unroll
            for (int dr = -1; dr <= 1; dr++) {
                int rr = r + dr; rr = rr < 0 ? 0 : (rr > RG - 1 ? RG - 1 : rr);
                bool rin = interior || ((oy + rr >= 0) & (oy + rr < IMG));
#pragma unroll
                for (int dc = -1; dc <= 1; dc++) {
                    int cc = c + dc; cc = cc < 0 ? 0 : (cc > RG - 1 ? RG - 1 : cc);
                    bool nin = rin && (interior || ((ox + cc >= 0) & (ox + cc < IMG)));
                    float2 v = A2[rr * RSTR2 + cc];
                    mxp = fmaxf(mxp, nin ? v.x : -FINF);
                    mnp = fminf(mnp, nin ? v.x :  FINF);
                    mxg = fmaxf(mxg, nin ? v.y : -FINF);
                    mng = fminf(mng, nin ? v.y :  FINF);
                }
            }
            bnd = make_float2(mxp - mnp, mxg - mng);
        }
        B2[r * RSTR2 + c] = bnd;
        if ((r >= HALO) & (r < HALO + OT) & (c >= HALO) & (c < HALO + OT))
            C2[(r - HALO) * CSTR2 + (c - HALO)] = bnd;
    }
    __syncthreads();

    // ---- dilation cascade: maxpool_{2d+1} via iterated separable 3x3, d = 1..10
    {
        const int cA  = tid % RG;  const int rA0 = (tid / RG) * PXT;
        const int rB  = tid % RG;  const int cB0 = (tid / RG) * PXT;
        const bool rowown = (rB >= HALO) & (rB < HALO + OT) & ((oy + rB) < IMG);
        const int chi = (HALO + OT) < (IMG - ox) ? (HALO + OT) : (IMG - ox);
        const float2* crow = C2 + (rB - HALO) * CSTR2;

        for (int d = 1; d <= 10; d++) {
            // vertical max3: A2 = vmax3(B2), PXT rows of column cA
            {
                float2 prev = B2[(rA0 > 0 ? rA0 - 1 : 0) * RSTR2 + cA];
                float2 cur  = B2[rA0 * RSTR2 + cA];
#pragma unroll
                for (int i = 0; i < PXT; i++) {
                    int r = rA0 + i;
                    float2 nxt = B2[(r < RG - 1 ? r + 1 : RG - 1) * RSTR2 + cA];
                    A2[r * RSTR2 + cA] = fmax2(prev, fmax2(cur, nxt));
                    prev = cur; cur = nxt;
                }
            }
            __syncthreads();
            // horizontal max3: B2 = hmax3(A2), fused |.| accumulation on owned px
            {
                float2 prev = A2[rB * RSTR2 + (cB0 > 0 ? cB0 - 1 : 0)];
                float2 cur  = A2[rB * RSTR2 + cB0];
                float s = 0.f;
#pragma unroll
                for (int i = 0; i < PXT; i++) {
                    int c = cB0 + i;
                    float2 nxt = A2[rB * RSTR2 + (c < RG - 1 ? c + 1 : RG - 1)];
                    float2 v = fmax2(prev, fmax2(cur, nxt));
                    B2[rB * RSTR2 + c] = v;
                    if (rowown & (c >= HALO) & (c < chi)) {
                        float2 cc = crow[c - HALO];  // (pred_b, gt_b)
                        s += fabsf(v.x - cc.y) + fabsf(v.y - cc.x);
                    }
                    prev = cur; cur = nxt;
                }
                a_hd += (0.1f * (float)d) * s;
            }
            __syncthreads();
        }
    }

    // ---- block reduction -> per-tile partials (no atomics for the sums)
    const unsigned FULL = 0xffffffffu;
#pragma unroll
    for (int o = 16; o; o >>= 1) {
        a_bce += __shfl_down_sync(FULL, a_bce, o);
        a_hd  += __shfl_down_sync(FULL, a_hd,  o);
        a_p   += __shfl_down_sync(FULL, a_p,   o);
        a_t   += __shfl_down_sync(FULL, a_t,   o);
        a_pt  += __shfl_down_sync(FULL, a_pt,  o);
    }
    int lane = tid & 31, w = tid >> 5;               // 24 warps
    if (lane == 0) {
        red[w] = a_bce; red[24 + w] = a_hd; red[48 + w] = a_p;
        red[72 + w] = a_t; red[96 + w] = a_pt;
    }
    __syncthreads();
    if (tid == 0) {
        float sb = 0, sh = 0, sp = 0, st = 0, spt = 0;
#pragma unroll
        for (int i = 0; i < 24; i++) {
            sb += red[i]; sh += red[24 + i]; sp += red[48 + i];
            st += red[72 + i]; spt += red[96 + i];
        }
        float* g = &g_part[tile * 5];
        g[0] = sb; g[1] = sh; g[2] = sp; g[3] = st; g[4] = spt;
        __threadfence();
        unsigned v = atomicAdd(&g_count, 1u);
        red[120] = (v == NTILES - 1) ? 1.f : 0.f;
    }
    __syncthreads();

    // ---- last CTA performs the final combine (single-launch pipeline)
    if (red[120] != 0.f) {
        __threadfence();
        __shared__ float simg[16][2];   // (1-dice), ft per image
        __shared__ float sbh[16][2];    // bce, hd per image
        if (w < 16) {
            float bce = 0, hd = 0, p = 0, t = 0, pt = 0;
            for (int i = lane; i < TPD * TPD; i += 32) {
                const float* g = &g_part[(w * TPD * TPD + i) * 5];
                bce += g[0]; hd += g[1]; p += g[2]; t += g[3]; pt += g[4];
            }
#pragma unroll
            for (int o = 16; o; o >>= 1) {
                bce += __shfl_down_sync(FULL, bce, o);
                hd  += __shfl_down_sync(FULL, hd,  o);
                p   += __shfl_down_sync(FULL, p,   o);
                t   += __shfl_down_sync(FULL, t,   o);
                pt  += __shfl_down_sync(FULL, pt,  o);
            }
            if (lane == 0) {
                float dice = (2.f * pt + 1e-6f) / (p + t + 1e-6f + 1e-7f);
                float FP = p - pt, FN = t - pt;
                float tv = (pt + 1e-6f) / (pt + 0.7f * FP + 0.3f * FN + 1e-6f + 1e-7f);
                simg[w][0] = 1.f - dice;
                simg[w][1] = powf(fmaxf(1.f - tv, 0.f), 0.75f);
                sbh[w][0] = bce; sbh[w][1] = hd;
            }
        }
        __syncthreads();
        if (tid == 0) {
            float ds = 0, fs = 0, sb = 0, sh = 0;
#pragma unroll
            for (int i = 0; i < 16; i++) {
                ds += simg[i][0]; fs += simg[i][1];
                sb += sbh[i][0];  sh += sbh[i][1];
            }
            const float N = (float)NB * IMG * IMG;
            out[0] = sb / N + ds / 16.f + fs / 16.f +
                     0.1f * ((sh / N) / (5.5f + 1e-8f));
            g_count = 0;   // self-reset for next graph replay
        }
    }
}

extern "C" void kernel_launch(void* const* d_in, const int* in_sizes, int n_in,
                              void* d_out, int out_size) {
    const float* logits = (const float*)d_in[0];
    const int*   target = (const int*)d_in[1];
    cudaFuncSetAttribute(k_main, cudaFuncAttributeMaxDynamicSharedMemorySize, SMEM_BYTES);
    k_main<<<NTILES, NTHR, SMEM_BYTES>>>(logits, target, (float*)d_out);
}

// round 5
// speedup vs baseline: 2.8838x; 1.6425x over previous
#include <cuda_runtime.h>
#include <cuda_fp16.h>
#include <math.h>
#include <math_constants.h>

#define IMG   512
#define NB    16
#define OT    74          // owned (output) tile
#define RG    96          // region = OT + 2*HALO
#define HALO  11          // 1 (boundary) + 10 (dilation cascade)
#define TPD   7
#define NTILES (NB*TPD*TPD)   // 784
#define RSTR  97          // half2 row stride (odd -> conflict-free col walks)
#define CSTR  75          // center buffer half2 stride (odd)
#define NTHR  576         // 18 warps; 2 CTAs/SM
#define PXT   16          // 96*96/576
#define SEG   16          // cascade rows/cols per thread (96/6)

#define OFF_B   (RG*RSTR)            // 9312 (half2 units)
#define OFF_C   (2*RG*RSTR)          // 18624
#define OFF_RED (OFF_C + OT*CSTR)    // 24174
#define SMEM_H2 (OFF_RED + 104)      // 104 half2 units = 104 floats >= 97 used
#define SMEM_BYTES (SMEM_H2*4)       // ~94.8 KB -> 2 CTAs/SM

// per-tile partials: [tile][0]=bce [1]=hd [2]=p [3]=t [4]=pt (fully rewritten every launch)
__device__ float g_part[NTILES*5];
__device__ unsigned g_count;   // last-CTA counter; finisher resets to 0

__global__ void __launch_bounds__(NTHR, 2)
k_main(const float* __restrict__ logits, const int* __restrict__ target,
       float* __restrict__ out) {
    extern __shared__ __half2 sm[];
    __half2* A  = sm;            // temp (v-pass out) / raw (p,t)
    __half2* B  = sm + OFF_B;    // current (pred,gt) maps
    __half2* C  = sm + OFF_C;    // center boundaries (pred_b, gt_b), 74x74
    float*   red = (float*)(sm + OFF_RED);

    const int tid  = threadIdx.x;
    const int tile = blockIdx.x;
    const int b    = tile / (TPD * TPD);
    const int tr   = tile % (TPD * TPD);
    const int tyi  = tr / TPD, txi = tr % TPD;
    const int oy   = tyi * OT - HALO, ox = txi * OT - HALO;
    const bool interior = (oy >= 0) & (ox >= 0) & (oy + RG <= IMG) & (ox + RG <= IMG);

    const float* lg = logits + (size_t)b * IMG * IMG;
    const int*   tg = target + (size_t)b * IMG * IMG;

    const __half   hNI = __ushort_as_half((unsigned short)0xFC00);  // -inf
    const __half   hPI = __ushort_as_half((unsigned short)0x7C00);  // +inf
    const __half2  hNEG = __halves2half2(hNI, hNI);
    const __half2  hPOS = __halves2half2(hPI, hPI);

    float a_bce = 0.f, a_p = 0.f, a_t = 0.f, a_pt = 0.f, a_hd = 0.f;

    // ---- load: A = half2(sigmoid(x), t); elementwise loss partials on owned px
#pragma unroll
    for (int k = 0; k < PXT; k++) {
        int idx = tid + k * NTHR;
        int r = idx / RG, c = idx - r * RG;
        int iy = oy + r, ix = ox + c;
        bool in = interior || ((iy >= 0) & (iy < IMG) & (ix >= 0) & (ix < IMG));
        float p = 0.f, t = 0.f;
        if (in) {
            float x = lg[iy * IMG + ix];
            t = (float)tg[iy * IMG + ix];
            p = 1.f / (1.f + expf(-x));
            if ((r >= HALO) & (r < HALO + OT) & (c >= HALO) & (c < HALO + OT)) {
                a_bce += fmaxf(x, 0.f) - x * t + log1pf(expf(-fabsf(x)));
                a_p += p; a_t += t; a_pt += p * t;
            }
        }
        A[r * RSTR + c] = __floats2half2_rn(p, t);
    }
    __syncthreads();

    // ---- boundary: B = maxpool3 - minpool3 (-inf outside image)
#pragma unroll
    for (int k = 0; k < PXT; k++) {
        int idx = tid + k * NTHR;
        int r = idx / RG, c = idx - r * RG;
        int iy = oy + r, ix = ox + c;
        bool cin = interior || ((iy >= 0) & (iy < IMG) & (ix >= 0) & (ix < IMG));
        __half2 bnd = hNEG;
        if (cin) {
            __half2 mx = hNEG, mn = hPOS;
#pragma unroll
            for (int dr = -1; dr <= 1; dr++) {
                int rr = r + dr; rr = rr < 0 ? 0 : (rr > RG - 1 ? RG - 1 : rr);
                bool rin = interior || ((oy + rr >= 0) & (oy + rr < IMG));
#pragma unroll
                for (int dc = -1; dc <= 1; dc++) {
                    int cc = c + dc; cc = cc < 0 ? 0 : (cc > RG - 1 ? RG - 1 : cc);
                    bool nin = rin && (interior || ((ox + cc >= 0) & (ox + cc < IMG)));
                    __half2 v = A[rr * RSTR + cc];
                    mx = __hmax2(mx, nin ? v : hNEG);
                    mn = __hmin2(mn, nin ? v : hPOS);
                }
            }
            bnd = __hsub2(mx, mn);
        }
        B[r * RSTR + c] = bnd;
        if ((r >= HALO) & (r < HALO + OT) & (c >= HALO) & (c < HALO + OT))
            C[(r - HALO) * CSTR + (c - HALO)] = bnd;
    }
    __syncthreads();

    // ---- dilation cascade: maxpool_{2d+1} via iterated separable 3x3, d = 1..10
    {
        const int cA  = tid % RG;  const int rA0 = (tid / RG) * SEG;
        const int rB  = tid % RG;  const int cB0 = (tid / RG) * SEG;
        const bool rowown = (rB >= HALO) & (rB < HALO + OT) & ((oy + rB) < IMG);
        const int chi = (HALO + OT) < (IMG - ox) ? (HALO + OT) : (IMG - ox);
        const __half2* crow = C + (rB - HALO) * CSTR;

        for (int d = 1; d <= 10; d++) {
            // vertical max3: A = vmax3(B), SEG rows of column cA
            {
                __half2 prev = B[(rA0 > 0 ? rA0 - 1 : 0) * RSTR + cA];
                __half2 cur  = B[rA0 * RSTR + cA];
#pragma unroll
                for (int i = 0; i < SEG; i++) {
                    int r = rA0 + i;
                    __half2 nxt = B[(r < RG - 1 ? r + 1 : RG - 1) * RSTR + cA];
                    A[r * RSTR + cA] = __hmax2(prev, __hmax2(cur, nxt));
                    prev = cur; cur = nxt;
                }
            }
            __syncthreads();
            // horizontal max3: B = hmax3(A), fused |.| accumulation on owned px
            {
                __half2 prev = A[rB * RSTR + (cB0 > 0 ? cB0 - 1 : 0)];
                __half2 cur  = A[rB * RSTR + cB0];
                float s = 0.f;
#pragma unroll
                for (int i = 0; i < SEG; i++) {
                    int c = cB0 + i;
                    __half2 nxt = A[rB * RSTR + (c < RG - 1 ? c + 1 : RG - 1)];
                    __half2 v = __hmax2(prev, __hmax2(cur, nxt));
                    B[rB * RSTR + c] = v;
                    if (rowown & (c >= HALO) & (c < chi)) {
                        // cc = (pred_b, gt_b); need |pred_d-gt_b| + |gt_d-pred_b|
                        __half2 cc = __lowhigh2highlow(crow[c - HALO]);
                        float2 f = __half22float2(__habs2(__hsub2(v, cc)));
                        s += f.x + f.y;
                    }
                    prev = cur; cur = nxt;
                }
                a_hd += (0.1f * (float)d) * s;
            }
            __syncthreads();
        }
    }

    // ---- block reduction -> per-tile partials
    const unsigned FULL = 0xffffffffu;
#pragma unroll
    for (int o = 16; o; o >>= 1) {
        a_bce += __shfl_down_sync(FULL, a_bce, o);
        a_hd  += __shfl_down_sync(FULL, a_hd,  o);
        a_p   += __shfl_down_sync(FULL, a_p,   o);
        a_t   += __shfl_down_sync(FULL, a_t,   o);
        a_pt  += __shfl_down_sync(FULL, a_pt,  o);
    }
    int lane = tid & 31, w = tid >> 5;               // 18 warps
    if (lane == 0) {
        red[w] = a_bce; red[18 + w] = a_hd; red[36 + w] = a_p;
        red[54 + w] = a_t; red[72 + w] = a_pt;
    }
    __syncthreads();
    if (tid == 0) {
        float sb = 0, sh = 0, sp = 0, st = 0, spt = 0;
#pragma unroll
        for (int i = 0; i < 18; i++) {
            sb += red[i]; sh += red[18 + i]; sp += red[36 + i];
            st += red[54 + i]; spt += red[72 + i];
        }
        float* g = &g_part[tile * 5];
        g[0] = sb; g[1] = sh; g[2] = sp; g[3] = st; g[4] = spt;
        __threadfence();
        unsigned v = atomicAdd(&g_count, 1u);
        red[96] = (v == NTILES - 1) ? 1.f : 0.f;
    }
    __syncthreads();

    // ---- last CTA performs the final combine (single-launch pipeline)
    if (red[96] != 0.f) {
        __threadfence();
        __shared__ float simg[16][2];   // (1-dice), ft per image
        __shared__ float sbh[16][2];    // bce, hd per image
        for (int img = w; img < 16; img += 18) {
            float bce = 0, hd = 0, p = 0, t = 0, pt = 0;
            for (int i = lane; i < TPD * TPD; i += 32) {
                const float* g = &g_part[(img * TPD * TPD + i) * 5];
                bce += g[0]; hd += g[1]; p += g[2]; t += g[3]; pt += g[4];
            }
#pragma unroll
            for (int o = 16; o; o >>= 1) {
                bce += __shfl_down_sync(FULL, bce, o);
                hd  += __shfl_down_sync(FULL, hd,  o);
                p   += __shfl_down_sync(FULL, p,   o);
                t   += __shfl_down_sync(FULL, t,   o);
                pt  += __shfl_down_sync(FULL, pt,  o);
            }
            if (lane == 0) {
                float dice = (2.f * pt + 1e-6f) / (p + t + 1e-6f + 1e-7f);
                float FP = p - pt, FN = t - pt;
                float tv = (pt + 1e-6f) / (pt + 0.7f * FP + 0.3f * FN + 1e-6f + 1e-7f);
                simg[img][0] = 1.f - dice;
                simg[img][1] = powf(fmaxf(1.f - tv, 0.f), 0.75f);
                sbh[img][0] = bce; sbh[img][1] = hd;
            }
        }
        __syncthreads();
        if (tid == 0) {
            float ds = 0, fs = 0, sb = 0, sh = 0;
#pragma unroll
            for (int i = 0; i < 16; i++) {
                ds += simg[i][0]; fs += simg[i][1];
                sb += sbh[i][0];  sh += sbh[i][1];
            }
            const float N = (float)NB * IMG * IMG;
            out[0] = sb / N + ds / 16.f + fs / 16.f +
                     0.1f * ((sh / N) / (5.5f + 1e-8f));
            g_count = 0;   // self-reset for next graph replay
        }
    }
}

extern "C" void kernel_launch(void* const* d_in, const int* in_sizes, int n_in,
                              void* d_out, int out_size) {
    const float* logits = (const float*)d_in[0];
    const int*   target = (const int*)d_in[1];
    cudaFuncSetAttribute(k_main, cudaFuncAttributeMaxDynamicSharedMemorySize, SMEM_BYTES);
    k_main<<<NTILES, NTHR, SMEM_BYTES>>>(logits, target, (float*)d_out);
}